// round 1
// baseline (speedup 1.0000x reference)
#include <cuda_runtime.h>
#include <cuda_bf16.h>

// Problem constants (fixed by setup_inputs)
#define BD   4      // batch
#define CH   32     // channels
#define NH   4      // heads
#define HD   8      // head_dim
#define HH   256
#define WW   256
#define KS   5      // kernel size (2*amp+1)
#define AMP  2

// Tiling
#define TILE_Y 16
#define TILE_X 32
#define TXN    8            // threads along x
#define P      4            // pixels per thread along x
#define NTHR   128          // TXN * TILE_Y / ... -> 8 x 16
#define SROWS  (TILE_Y + 2*AMP)   // 20
#define SCOLS  (TILE_X + 2*AMP)   // 36

__global__ __launch_bounds__(NTHR, 3)
void cover_kernel(const float* __restrict__ xq,
                  const float* __restrict__ xk,
                  float* __restrict__ out)
{
    // per-head k tile: 8 channels x 20 rows x 36 cols = 23040 B
    __shared__ float sk[HD][SROWS][SCOLS];

    const int tid = threadIdx.x;
    const int tx  = tid & (TXN - 1);   // 0..7
    const int ty  = tid >> 3;          // 0..15
    const int x0  = blockIdx.x * TILE_X;
    const int y0  = blockIdx.y * TILE_Y;
    const int b   = blockIdx.z;
    const int y   = y0 + ty;
    const int xg  = x0 + tx * P;

    // validity bitmasks (offset index di/dj in 0..4 maps to offset di-2 / dj-2)
    unsigned rowbits = 0;
    #pragma unroll
    for (int di = 0; di < KS; ++di) {
        int yy = y + di - AMP;
        if (yy >= 0 && yy < HH) rowbits |= (1u << di);
    }
    unsigned colbits[P];
    #pragma unroll
    for (int p = 0; p < P; ++p) {
        unsigned cb = 0;
        #pragma unroll
        for (int dj = 0; dj < KS; ++dj) {
            int xx = xg + p + dj - AMP;
            if (xx >= 0 && xx < WW) cb |= (1u << dj);
        }
        colbits[p] = cb;
    }

    const float scale = 0.35355339059327373f;  // 8^-0.5
    const long  plane = (long)HH * WW;

    const float* xq_b = xq + (long)b * CH * plane;
    const float* xk_b = xk + (long)b * CH * plane;

    float outy[P] = {0.f, 0.f, 0.f, 0.f};
    float outx[P] = {0.f, 0.f, 0.f, 0.f};

    for (int h = 0; h < NH; ++h) {
        __syncthreads();  // previous head's tile fully consumed

        // stage k tile for this head: channels c = d*NH + h, d in [0,8)
        for (int idx = tid; idx < HD * SROWS * SCOLS; idx += NTHR) {
            int c   = idx / (SROWS * SCOLS);
            int rem = idx - c * (SROWS * SCOLS);
            int r   = rem / SCOLS;
            int m   = rem - r * SCOLS;
            int gy  = y0 - AMP + r;
            int gx  = x0 - AMP + m;
            float v = 0.f;
            if (gy >= 0 && gy < HH && gx >= 0 && gx < WW)
                v = xk_b[(long)(c * NH + h) * plane + (long)gy * WW + gx];
            sk[c][r][m] = v;
        }
        __syncthreads();

        // 25 offset-dot accumulators for 4 pixels
        float acc[KS * KS][P];
        #pragma unroll
        for (int k = 0; k < KS * KS; ++k)
            #pragma unroll
            for (int p = 0; p < P; ++p) acc[k][p] = 0.f;

        #pragma unroll
        for (int c = 0; c < HD; ++c) {
            // q for this channel, 4 pixels (aligned float4: xg multiple of 4)
            float4 qv = *reinterpret_cast<const float4*>(
                xq_b + (long)(c * NH + h) * plane + (long)y * WW + xg);
            float q[P] = {qv.x * scale, qv.y * scale, qv.z * scale, qv.w * scale};

            #pragma unroll
            for (int di = 0; di < KS; ++di) {
                const float* krow = &sk[c][ty + di][tx * P];  // 16B aligned
                float4 k0 = *reinterpret_cast<const float4*>(krow);
                float4 k1 = *reinterpret_cast<const float4*>(krow + 4);
                float kk[8] = {k0.x, k0.y, k0.z, k0.w, k1.x, k1.y, k1.z, k1.w};
                #pragma unroll
                for (int dj = 0; dj < KS; ++dj)
                    #pragma unroll
                    for (int p = 0; p < P; ++p)
                        acc[di * KS + dj][p] =
                            fmaf(q[p], kk[p + dj], acc[di * KS + dj][p]);
            }
        }

        // per-pixel softmax over 25 offsets + offset-weighted reduction
        #pragma unroll
        for (int p = 0; p < P; ++p) {
            const unsigned cb = colbits[p];
            float m = -3.0e38f;
            #pragma unroll
            for (int di = 0; di < KS; ++di)
                #pragma unroll
                for (int dj = 0; dj < KS; ++dj) {
                    bool valid = ((rowbits >> di) & 1u) && ((cb >> dj) & 1u);
                    float a = valid ? acc[di * KS + dj][p] : -3.0e38f;
                    m = fmaxf(m, a);
                }
            float s = 0.f, oy = 0.f, ox = 0.f;
            #pragma unroll
            for (int di = 0; di < KS; ++di)
                #pragma unroll
                for (int dj = 0; dj < KS; ++dj) {
                    bool valid = ((rowbits >> di) & 1u) && ((cb >> dj) & 1u);
                    float w = valid ? __expf(acc[di * KS + dj][p] - m) : 0.f;
                    s += w;
                    oy += w * (float)(di - AMP);
                    ox += w * (float)(dj - AMP);
                }
            float inv = __frcp_rn(s);
            outy[p] += oy * inv;
            outx[p] += ox * inv;
        }
    }

    // mean over heads, write (B, 2, H, W): ch0 = row offset, ch1 = col offset
    const float invh = 1.0f / (float)NH;
    float* ob = out + (long)b * 2 * plane;
    float4 o0 = make_float4(outy[0] * invh, outy[1] * invh,
                            outy[2] * invh, outy[3] * invh);
    float4 o1 = make_float4(outx[0] * invh, outx[1] * invh,
                            outx[2] * invh, outx[3] * invh);
    *reinterpret_cast<float4*>(ob + (long)y * WW + xg) = o0;
    *reinterpret_cast<float4*>(ob + plane + (long)y * WW + xg) = o1;
}

extern "C" void kernel_launch(void* const* d_in, const int* in_sizes, int n_in,
                              void* d_out, int out_size)
{
    const float* xq = (const float*)d_in[0];
    const float* xk = (const float*)d_in[1];
    float* out = (float*)d_out;
    (void)in_sizes; (void)n_in; (void)out_size;

    dim3 grid(WW / TILE_X, HH / TILE_Y, BD);  // (8, 16, 4)
    cover_kernel<<<grid, NTHR>>>(xq, xk, out);
}